// round 11
// baseline (speedup 1.0000x reference)
#include <cuda_runtime.h>
#include <math.h>

#define N_NODES 100000
#define E_MAX   1600000
#define DIN 64
#define DH 128
#define DOUT 64

typedef unsigned long long u64;

// Scratch (device globals: allocation-free rule).
__device__ __align__(16) int   g_cnt[N_NODES];
__device__ __align__(16) int   g_start[N_NODES];
__device__ __align__(16) int   g_cur[N_NODES];
__device__ __align__(16) int   g_csr[E_MAX];
__device__ __align__(16) float g_agg1[(size_t)N_NODES * DIN];
__device__ __align__(16) float g_h[(size_t)N_NODES * DH];
__device__ __align__(16) float g_t[(size_t)N_NODES * DOUT];
__device__ __align__(16) float g_h2[(size_t)N_NODES * DOUT];

// ---------------------------------------------------------------- f32x2 helpers
__device__ __forceinline__ u64 pk2(float lo, float hi) {
    u64 r;
    asm("mov.b64 %0, {%1, %2};" : "=l"(r) : "f"(lo), "f"(hi));
    return r;
}
__device__ __forceinline__ void upk2(u64 v, float& lo, float& hi) {
    asm("mov.b64 {%0, %1}, %2;" : "=f"(lo), "=f"(hi) : "l"(v));
}
__device__ __forceinline__ u64 ffma2(u64 a, u64 b, u64 c) {
    u64 d;
    asm("fma.rn.f32x2 %0, %1, %2, %3;" : "=l"(d) : "l"(a), "l"(b), "l"(c));
    return d;
}

// ---------------------------------------------------------------- CSR build
__global__ void zero_cnt_kernel() {
    int i = blockIdx.x * blockDim.x + threadIdx.x;
    if (i < N_NODES) g_cnt[i] = 0;
}

// edge_index int32, layout [2, E]. 8 edges per thread.
__global__ void hist_kernel(const int* __restrict__ ei, int E) {
    int i = blockIdx.x * blockDim.x + threadIdx.x;
    int e8 = i * 8;
    if (e8 + 7 < E) {
        int4 a = *(const int4*)&ei[E + e8];
        int4 b = *(const int4*)&ei[E + e8 + 4];
        atomicAdd(&g_cnt[a.x], 1);
        atomicAdd(&g_cnt[a.y], 1);
        atomicAdd(&g_cnt[a.z], 1);
        atomicAdd(&g_cnt[a.w], 1);
        atomicAdd(&g_cnt[b.x], 1);
        atomicAdd(&g_cnt[b.y], 1);
        atomicAdd(&g_cnt[b.z], 1);
        atomicAdd(&g_cnt[b.w], 1);
    } else {
        for (int e = e8; e < E; e++) atomicAdd(&g_cnt[ei[E + e]], 1);
    }
}

// Single-block scan of 100k counts; 1000 active threads x 100 elems, int4 I/O.
__global__ void scan_kernel() {
    __shared__ int partial[1024];
    int t = threadIdx.x;
    int s = 0;
    if (t < 1000) {
        const int4* c4 = (const int4*)&g_cnt[t * 100];
#pragma unroll
        for (int i = 0; i < 25; i++) {
            int4 v = c4[i];
            s += v.x + v.y + v.z + v.w;
        }
    }
    partial[t] = s;
    __syncthreads();
    for (int off = 1; off < 1024; off <<= 1) {
        int v = partial[t];
        int add = (t >= off) ? partial[t - off] : 0;
        __syncthreads();
        partial[t] = v + add;
        __syncthreads();
    }
    if (t < 1000) {
        int run = (t == 0) ? 0 : partial[t - 1];
        const int4* c4 = (const int4*)&g_cnt[t * 100];
        int4* s4 = (int4*)&g_start[t * 100];
        int4* u4 = (int4*)&g_cur[t * 100];
#pragma unroll
        for (int i = 0; i < 25; i++) {
            int4 c = c4[i];
            int4 st;
            st.x = run; run += c.x;
            st.y = run; run += c.y;
            st.z = run; run += c.z;
            st.w = run; run += c.w;
            s4[i] = st;
            u4[i] = st;
        }
    }
}

__global__ void fill_kernel(const int* __restrict__ ei, int E) {
    int i = blockIdx.x * blockDim.x + threadIdx.x;
    int e8 = i * 8;
    if (e8 + 7 < E) {
        int4 sa = *(const int4*)&ei[e8];
        int4 sb = *(const int4*)&ei[e8 + 4];
        int4 da = *(const int4*)&ei[E + e8];
        int4 db = *(const int4*)&ei[E + e8 + 4];
        g_csr[atomicAdd(&g_cur[da.x], 1)] = sa.x;
        g_csr[atomicAdd(&g_cur[da.y], 1)] = sa.y;
        g_csr[atomicAdd(&g_cur[da.z], 1)] = sa.z;
        g_csr[atomicAdd(&g_cur[da.w], 1)] = sa.w;
        g_csr[atomicAdd(&g_cur[db.x], 1)] = sb.x;
        g_csr[atomicAdd(&g_cur[db.y], 1)] = sb.y;
        g_csr[atomicAdd(&g_cur[db.z], 1)] = sb.z;
        g_csr[atomicAdd(&g_cur[db.w], 1)] = sb.w;
    } else {
        for (int e = e8; e < E; e++)
            g_csr[atomicAdd(&g_cur[ei[E + e]], 1)] = ei[e];
    }
}

// ------------------------------------------------- aggregation 1: gather-mean of x rows
// Warp per node; half-warp per edge (2 edges/iter), float4 per lane (16 lanes cover 64 dims).
__global__ void agg1_kernel(const float* __restrict__ x) {
    int gw = (blockIdx.x * blockDim.x + threadIdx.x) >> 5;
    int lane = threadIdx.x & 31;
    int hl = lane >> 4, ll = lane & 15;
    int nwarps = (gridDim.x * blockDim.x) >> 5;
    const float4* x4 = (const float4*)x;
    for (int node = gw; node < N_NODES; node += nwarps) {
        int beg = g_start[node];
        int d = g_cnt[node];
        float4 a = make_float4(0.f, 0.f, 0.f, 0.f);
        int e = 0;
        for (; e + 4 <= d; e += 4) {
            int s0 = g_csr[beg + e + hl];
            int s1 = g_csr[beg + e + 2 + hl];
            float4 v0 = x4[(size_t)s0 * 16 + ll];
            float4 v1 = x4[(size_t)s1 * 16 + ll];
            a.x += v0.x + v1.x; a.y += v0.y + v1.y;
            a.z += v0.z + v1.z; a.w += v0.w + v1.w;
        }
        for (; e < d; e += 2) {
            if (e + hl < d) {
                int s0 = g_csr[beg + e + hl];
                float4 v0 = x4[(size_t)s0 * 16 + ll];
                a.x += v0.x; a.y += v0.y; a.z += v0.z; a.w += v0.w;
            }
        }
        a.x += __shfl_xor_sync(0xFFFFFFFFu, a.x, 16);
        a.y += __shfl_xor_sync(0xFFFFFFFFu, a.y, 16);
        a.z += __shfl_xor_sync(0xFFFFFFFFu, a.z, 16);
        a.w += __shfl_xor_sync(0xFFFFFFFFu, a.w, 16);
        if (hl == 0) {
            float invd = 1.0f / fmaxf((float)d, 1.0f);
            a.x *= invd; a.y *= invd; a.z *= invd; a.w *= invd;
            ((float4*)g_agg1)[(size_t)node * 16 + ll] = a;
        }
    }
}

// ------------------------------------------------- aggregation 2: gather-mean of t, fused += h2
__global__ void agg2_kernel() {
    int gw = (blockIdx.x * blockDim.x + threadIdx.x) >> 5;
    int lane = threadIdx.x & 31;
    int hl = lane >> 4, ll = lane & 15;
    int nwarps = (gridDim.x * blockDim.x) >> 5;
    const float4* t4 = (const float4*)g_t;
    for (int node = gw; node < N_NODES; node += nwarps) {
        int beg = g_start[node];
        int d = g_cnt[node];
        float4 a = make_float4(0.f, 0.f, 0.f, 0.f);
        int e = 0;
        for (; e + 4 <= d; e += 4) {
            int s0 = g_csr[beg + e + hl];
            int s1 = g_csr[beg + e + 2 + hl];
            float4 v0 = t4[(size_t)s0 * 16 + ll];
            float4 v1 = t4[(size_t)s1 * 16 + ll];
            a.x += v0.x + v1.x; a.y += v0.y + v1.y;
            a.z += v0.z + v1.z; a.w += v0.w + v1.w;
        }
        for (; e < d; e += 2) {
            if (e + hl < d) {
                int s0 = g_csr[beg + e + hl];
                float4 v0 = t4[(size_t)s0 * 16 + ll];
                a.x += v0.x; a.y += v0.y; a.z += v0.z; a.w += v0.w;
            }
        }
        a.x += __shfl_xor_sync(0xFFFFFFFFu, a.x, 16);
        a.y += __shfl_xor_sync(0xFFFFFFFFu, a.y, 16);
        a.z += __shfl_xor_sync(0xFFFFFFFFu, a.z, 16);
        a.w += __shfl_xor_sync(0xFFFFFFFFu, a.w, 16);
        if (hl == 0) {
            float invd = 1.0f / fmaxf((float)d, 1.0f);
            float4* o = &((float4*)g_h2)[(size_t)node * 16 + ll];
            float4 cur = *o;
            cur.x += a.x * invd; cur.y += a.y * invd;
            cur.z += a.z * invd; cur.w += a.w * invd;
            *o = cur;
        }
    }
}

// ------------------------------------------------- layer 1 (combined GEMM, k=128, f32x2 packed)
// h[:, jb:jb+64] = relu([agg1|x] @ [W1l|W1r](jb:jb+64)^T + b1); gridDim.y picks j-half.
// 128 threads (4 warps); 8 nodes/warp as 4 packed pairs; stage holds float2{s_na, s_nb}.
__global__ void layer1_kernel(const float* __restrict__ x,
                              const float* __restrict__ W1l,
                              const float* __restrict__ W1r,
                              const float* __restrict__ b1) {
    __shared__ float  Wc[128 * 64];       // [k][jl], 32KB
    __shared__ float2 st2[4][4 * 128];    // [warp][pair*128+k], 16KB

    int tid = threadIdx.x;
    int jb = blockIdx.y * 64;
    for (int idx = tid; idx < 128 * 64; idx += 128) {
        int jl = idx & 63, k = idx >> 6;
        Wc[k * 64 + jl] = (k < 64) ? W1l[(size_t)(jb + jl) * 64 + k]
                                   : W1r[(size_t)(jb + jl) * 64 + (k - 64)];
    }
    __syncthreads();

    int warp = tid >> 5, lane = tid & 31;
    float2* st = st2[warp];
    float2 bv = *(const float2*)&b1[jb + lane * 2];
    u64 pb0 = pk2(bv.x, bv.x), pb1 = pk2(bv.y, bv.y);

    int wg = blockIdx.x * 4 + warp;
    int wstride = gridDim.x * 4;
    const int NG = N_NODES / 8;  // 12500

    for (int q = wg; q < NG; q += wstride) {
        int n0 = q * 8;
#pragma unroll
        for (int p = 0; p < 4; p++) {
            size_t na = (size_t)(n0 + 2 * p), nb = na + 1;
            st[p * 128 + lane]      = make_float2(g_agg1[na * 64 + lane],      g_agg1[nb * 64 + lane]);
            st[p * 128 + lane + 32] = make_float2(g_agg1[na * 64 + 32 + lane], g_agg1[nb * 64 + 32 + lane]);
            st[p * 128 + lane + 64] = make_float2(x[na * 64 + lane],           x[nb * 64 + lane]);
            st[p * 128 + lane + 96] = make_float2(x[na * 64 + 32 + lane],      x[nb * 64 + 32 + lane]);
        }
        __syncwarp();

        u64 acc[4][2];
#pragma unroll
        for (int p = 0; p < 4; p++) { acc[p][0] = pb0; acc[p][1] = pb1; }

#pragma unroll 4
        for (int k = 0; k < 128; k++) {
            float2 w = *(const float2*)&Wc[k * 64 + lane * 2];
            u64 wa = pk2(w.x, w.x), wb = pk2(w.y, w.y);
            u64 s0 = *(const u64*)&st[k];
            u64 s1 = *(const u64*)&st[128 + k];
            u64 s2 = *(const u64*)&st[256 + k];
            u64 s3 = *(const u64*)&st[384 + k];
            acc[0][0] = ffma2(s0, wa, acc[0][0]); acc[0][1] = ffma2(s0, wb, acc[0][1]);
            acc[1][0] = ffma2(s1, wa, acc[1][0]); acc[1][1] = ffma2(s1, wb, acc[1][1]);
            acc[2][0] = ffma2(s2, wa, acc[2][0]); acc[2][1] = ffma2(s2, wb, acc[2][1]);
            acc[3][0] = ffma2(s3, wa, acc[3][0]); acc[3][1] = ffma2(s3, wb, acc[3][1]);
        }

#pragma unroll
        for (int p = 0; p < 4; p++) {
            float lo0, hi0, lo1, hi1;
            upk2(acc[p][0], lo0, hi0);
            upk2(acc[p][1], lo1, hi1);
            *(float2*)&g_h[(size_t)(n0 + 2 * p) * 128 + jb + lane * 2] =
                make_float2(fmaxf(lo0, 0.f), fmaxf(lo1, 0.f));
            *(float2*)&g_h[(size_t)(n0 + 2 * p + 1) * 128 + jb + lane * 2] =
                make_float2(fmaxf(hi0, 0.f), fmaxf(hi1, 0.f));
        }
        __syncwarp();
    }
}

// ------------------------------------------------- layer 2 (two GEMMs via gridDim.y, f32x2 packed)
// y=0: g_t = h @ W2l^T; y=1: g_h2 = h @ W2r^T + b2.
__global__ void layer2_kernel(const float* __restrict__ W2l,
                              const float* __restrict__ W2r,
                              const float* __restrict__ b2) {
    __shared__ float  Wc[128 * 64];
    __shared__ float2 st2[4][4 * 128];

    int tid = threadIdx.x;
    int ysel = blockIdx.y;
    const float* W = ysel ? W2r : W2l;
    float* outbuf = ysel ? g_h2 : g_t;
    for (int idx = tid; idx < 128 * 64; idx += 128) {
        int jl = idx & 63, k = idx >> 6;
        Wc[k * 64 + jl] = W[(size_t)jl * 128 + k];
    }
    __syncthreads();

    int warp = tid >> 5, lane = tid & 31;
    float2* st = st2[warp];
    float2 bv = ysel ? *(const float2*)&b2[lane * 2] : make_float2(0.f, 0.f);
    u64 pb0 = pk2(bv.x, bv.x), pb1 = pk2(bv.y, bv.y);

    int wg = blockIdx.x * 4 + warp;
    int wstride = gridDim.x * 4;
    const int NG = N_NODES / 8;

    for (int q = wg; q < NG; q += wstride) {
        int n0 = q * 8;
#pragma unroll
        for (int p = 0; p < 4; p++) {
            size_t na = (size_t)(n0 + 2 * p), nb = na + 1;
            st[p * 128 + lane]      = make_float2(g_h[na * 128 + lane],      g_h[nb * 128 + lane]);
            st[p * 128 + lane + 32] = make_float2(g_h[na * 128 + 32 + lane], g_h[nb * 128 + 32 + lane]);
            st[p * 128 + lane + 64] = make_float2(g_h[na * 128 + 64 + lane], g_h[nb * 128 + 64 + lane]);
            st[p * 128 + lane + 96] = make_float2(g_h[na * 128 + 96 + lane], g_h[nb * 128 + 96 + lane]);
        }
        __syncwarp();

        u64 acc[4][2];
#pragma unroll
        for (int p = 0; p < 4; p++) { acc[p][0] = pb0; acc[p][1] = pb1; }

#pragma unroll 4
        for (int k = 0; k < 128; k++) {
            float2 w = *(const float2*)&Wc[k * 64 + lane * 2];
            u64 wa = pk2(w.x, w.x), wb = pk2(w.y, w.y);
            u64 s0 = *(const u64*)&st[k];
            u64 s1 = *(const u64*)&st[128 + k];
            u64 s2 = *(const u64*)&st[256 + k];
            u64 s3 = *(const u64*)&st[384 + k];
            acc[0][0] = ffma2(s0, wa, acc[0][0]); acc[0][1] = ffma2(s0, wb, acc[0][1]);
            acc[1][0] = ffma2(s1, wa, acc[1][0]); acc[1][1] = ffma2(s1, wb, acc[1][1]);
            acc[2][0] = ffma2(s2, wa, acc[2][0]); acc[2][1] = ffma2(s2, wb, acc[2][1]);
            acc[3][0] = ffma2(s3, wa, acc[3][0]); acc[3][1] = ffma2(s3, wb, acc[3][1]);
        }

#pragma unroll
        for (int p = 0; p < 4; p++) {
            float lo0, hi0, lo1, hi1;
            upk2(acc[p][0], lo0, hi0);
            upk2(acc[p][1], lo1, hi1);
            *(float2*)&outbuf[(size_t)(n0 + 2 * p) * 64 + lane * 2]     = make_float2(lo0, lo1);
            *(float2*)&outbuf[(size_t)(n0 + 2 * p + 1) * 64 + lane * 2] = make_float2(hi0, hi1);
        }
        __syncwarp();
    }
}

// ------------------------------------------------- link prediction: warp per pair, float2 loads
__global__ void predict_kernel(const int* __restrict__ pairs,
                               const float* __restrict__ Wlp,
                               const float* __restrict__ blp,
                               float* __restrict__ out, int P) {
    int g = blockIdx.x * blockDim.x + threadIdx.x;
    int p = g >> 5;
    int lane = g & 31;
    if (p >= P) return;
    int2 sd = *(const int2*)&pairs[p * 2];
    float2 ws = *(const float2*)&Wlp[lane * 2];
    float2 wd = *(const float2*)&Wlp[64 + lane * 2];
    float2 hs = *(const float2*)&g_h2[(size_t)sd.x * 64 + lane * 2];
    float2 hd = *(const float2*)&g_h2[(size_t)sd.y * 64 + lane * 2];
    float v = hs.x * ws.x + hs.y * ws.y + hd.x * wd.x + hd.y * wd.y;
#pragma unroll
    for (int o = 16; o; o >>= 1) v += __shfl_xor_sync(0xFFFFFFFFu, v, o);
    if (lane == 0) out[p] = 1.0f / (1.0f + expf(-(v + blp[0])));
}

// ----------------------------------------------------------------------------
extern "C" void kernel_launch(void* const* d_in, const int* in_sizes, int n_in,
                              void* d_out, int out_size) {
    const float* x   = (const float*)d_in[0];
    const int* ei    = (const int*)d_in[1];    // int32 (JAX x64 disabled)
    const int* prs   = (const int*)d_in[2];    // int32
    const float* W1l = (const float*)d_in[3];
    const float* W1r = (const float*)d_in[4];
    const float* b1  = (const float*)d_in[5];
    const float* W2l = (const float*)d_in[6];
    const float* W2r = (const float*)d_in[7];
    const float* b2  = (const float*)d_in[8];
    const float* Wlp = (const float*)d_in[9];
    const float* blp = (const float*)d_in[10];
    float* out       = (float*)d_out;

    int E = in_sizes[1] / 2;
    int P = in_sizes[2] / 2;
    int e8blocks = ((E + 7) / 8 + 255) / 256;

    // CSR build
    zero_cnt_kernel<<<(N_NODES + 255) / 256, 256>>>();
    hist_kernel<<<e8blocks, 256>>>(ei, E);
    scan_kernel<<<1, 1024>>>();
    fill_kernel<<<e8blocks, 256>>>(ei, E);

    // Layer 1
    agg1_kernel<<<1480, 256>>>(x);
    dim3 lgrid(1184, 2);
    layer1_kernel<<<lgrid, 128>>>(x, W1l, W1r, b1);

    // Layer 2 (linearity: aggregate t = h@W2l^T instead of h)
    layer2_kernel<<<lgrid, 128>>>(W2l, W2r, b2);
    agg2_kernel<<<1480, 256>>>();

    // Link prediction
    int pblocks = (P * 32 + 255) / 256;
    predict_kernel<<<pblocks, 256>>>(prs, Wlp, blp, out, P);
}

// round 13
// speedup vs baseline: 1.0152x; 1.0152x over previous
#include <cuda_runtime.h>
#include <math.h>

#define N_NODES 100000
#define E_MAX   1600000
#define DIN 64
#define DH 128
#define DOUT 64

// Scratch (device globals: allocation-free rule).
__device__ __align__(16) int   g_cnt[N_NODES];
__device__ __align__(16) int   g_start[N_NODES];
__device__ __align__(16) int   g_cur[N_NODES];
__device__ __align__(16) int   g_csr[E_MAX];
__device__ __align__(16) float g_agg1[(size_t)N_NODES * DIN];
__device__ __align__(16) float g_h[(size_t)N_NODES * DH];
__device__ __align__(16) float g_t[(size_t)N_NODES * DOUT];
__device__ __align__(16) float g_h2[(size_t)N_NODES * DOUT];

// ---------------------------------------------------------------- CSR build
__global__ void zero_cnt_kernel() {
    int i = blockIdx.x * blockDim.x + threadIdx.x;
    if (i < N_NODES) g_cnt[i] = 0;
}

// edge_index is int32, layout [2, E]. 4 edges per thread via int4.
__global__ void hist_kernel(const int* __restrict__ ei, int E) {
    int i = blockIdx.x * blockDim.x + threadIdx.x;
    int e4 = i * 4;
    if (e4 + 3 < E) {
        int4 d4 = *(const int4*)&ei[E + e4];
        atomicAdd(&g_cnt[d4.x], 1);
        atomicAdd(&g_cnt[d4.y], 1);
        atomicAdd(&g_cnt[d4.z], 1);
        atomicAdd(&g_cnt[d4.w], 1);
    } else {
        for (int e = e4; e < E; e++) atomicAdd(&g_cnt[ei[E + e]], 1);
    }
}

// Single-block scan of 100k counts; 1000 active threads x 100 elems, int4 I/O.
__global__ void scan_kernel() {
    __shared__ int partial[1024];
    int t = threadIdx.x;
    int s = 0;
    if (t < 1000) {
        const int4* c4 = (const int4*)&g_cnt[t * 100];
#pragma unroll
        for (int i = 0; i < 25; i++) {
            int4 v = c4[i];
            s += v.x + v.y + v.z + v.w;
        }
    }
    partial[t] = s;
    __syncthreads();
    for (int off = 1; off < 1024; off <<= 1) {
        int v = partial[t];
        int add = (t >= off) ? partial[t - off] : 0;
        __syncthreads();
        partial[t] = v + add;
        __syncthreads();
    }
    if (t < 1000) {
        int run = (t == 0) ? 0 : partial[t - 1];
        const int4* c4 = (const int4*)&g_cnt[t * 100];
        int4* s4 = (int4*)&g_start[t * 100];
        int4* u4 = (int4*)&g_cur[t * 100];
#pragma unroll
        for (int i = 0; i < 25; i++) {
            int4 c = c4[i];
            int4 st;
            st.x = run; run += c.x;
            st.y = run; run += c.y;
            st.z = run; run += c.z;
            st.w = run; run += c.w;
            s4[i] = st;
            u4[i] = st;
        }
    }
}

__global__ void fill_kernel(const int* __restrict__ ei, int E) {
    int i = blockIdx.x * blockDim.x + threadIdx.x;
    int e4 = i * 4;
    if (e4 + 3 < E) {
        int4 s4 = *(const int4*)&ei[e4];
        int4 d4 = *(const int4*)&ei[E + e4];
        g_csr[atomicAdd(&g_cur[d4.x], 1)] = s4.x;
        g_csr[atomicAdd(&g_cur[d4.y], 1)] = s4.y;
        g_csr[atomicAdd(&g_cur[d4.z], 1)] = s4.z;
        g_csr[atomicAdd(&g_cur[d4.w], 1)] = s4.w;
    } else {
        for (int e = e4; e < E; e++)
            g_csr[atomicAdd(&g_cur[ei[E + e]], 1)] = ei[e];
    }
}

// ------------------------------------------------- aggregation 1: gather-mean of x rows
// Warp per node; lane owns one float2 of the 64-dim row; 8 edges in flight (MLP=8).
__global__ void agg1_kernel(const float* __restrict__ x) {
    int gw = (blockIdx.x * blockDim.x + threadIdx.x) >> 5;
    int lane = threadIdx.x & 31;
    int nwarps = (gridDim.x * blockDim.x) >> 5;
    const float2* x2 = (const float2*)x;
    for (int node = gw; node < N_NODES; node += nwarps) {
        int beg = g_start[node];
        int d = g_cnt[node];
        float2 a = make_float2(0.f, 0.f);
        int e = 0;
        for (; e + 8 <= d; e += 8) {
            int s0 = g_csr[beg + e + 0];
            int s1 = g_csr[beg + e + 1];
            int s2 = g_csr[beg + e + 2];
            int s3 = g_csr[beg + e + 3];
            int s4 = g_csr[beg + e + 4];
            int s5 = g_csr[beg + e + 5];
            int s6 = g_csr[beg + e + 6];
            int s7 = g_csr[beg + e + 7];
            float2 v0 = x2[(size_t)s0 * 32 + lane];
            float2 v1 = x2[(size_t)s1 * 32 + lane];
            float2 v2 = x2[(size_t)s2 * 32 + lane];
            float2 v3 = x2[(size_t)s3 * 32 + lane];
            float2 v4 = x2[(size_t)s4 * 32 + lane];
            float2 v5 = x2[(size_t)s5 * 32 + lane];
            float2 v6 = x2[(size_t)s6 * 32 + lane];
            float2 v7 = x2[(size_t)s7 * 32 + lane];
            a.x += v0.x + v1.x + v2.x + v3.x + v4.x + v5.x + v6.x + v7.x;
            a.y += v0.y + v1.y + v2.y + v3.y + v4.y + v5.y + v6.y + v7.y;
        }
        for (; e + 4 <= d; e += 4) {
            int s0 = g_csr[beg + e + 0];
            int s1 = g_csr[beg + e + 1];
            int s2 = g_csr[beg + e + 2];
            int s3 = g_csr[beg + e + 3];
            float2 v0 = x2[(size_t)s0 * 32 + lane];
            float2 v1 = x2[(size_t)s1 * 32 + lane];
            float2 v2 = x2[(size_t)s2 * 32 + lane];
            float2 v3 = x2[(size_t)s3 * 32 + lane];
            a.x += v0.x + v1.x + v2.x + v3.x;
            a.y += v0.y + v1.y + v2.y + v3.y;
        }
        for (; e < d; e++) {
            int s0 = g_csr[beg + e];
            float2 v0 = x2[(size_t)s0 * 32 + lane];
            a.x += v0.x;
            a.y += v0.y;
        }
        float invd = 1.0f / fmaxf((float)d, 1.0f);
        ((float2*)g_agg1)[(size_t)node * 32 + lane] = make_float2(a.x * invd, a.y * invd);
    }
}

// ------------------------------------------------- aggregation 2: gather-mean of t, fused += h2
__global__ void agg2_kernel() {
    int gw = (blockIdx.x * blockDim.x + threadIdx.x) >> 5;
    int lane = threadIdx.x & 31;
    int nwarps = (gridDim.x * blockDim.x) >> 5;
    const float2* t2 = (const float2*)g_t;
    for (int node = gw; node < N_NODES; node += nwarps) {
        int beg = g_start[node];
        int d = g_cnt[node];
        float2 a = make_float2(0.f, 0.f);
        int e = 0;
        for (; e + 8 <= d; e += 8) {
            int s0 = g_csr[beg + e + 0];
            int s1 = g_csr[beg + e + 1];
            int s2 = g_csr[beg + e + 2];
            int s3 = g_csr[beg + e + 3];
            int s4 = g_csr[beg + e + 4];
            int s5 = g_csr[beg + e + 5];
            int s6 = g_csr[beg + e + 6];
            int s7 = g_csr[beg + e + 7];
            float2 v0 = t2[(size_t)s0 * 32 + lane];
            float2 v1 = t2[(size_t)s1 * 32 + lane];
            float2 v2 = t2[(size_t)s2 * 32 + lane];
            float2 v3 = t2[(size_t)s3 * 32 + lane];
            float2 v4 = t2[(size_t)s4 * 32 + lane];
            float2 v5 = t2[(size_t)s5 * 32 + lane];
            float2 v6 = t2[(size_t)s6 * 32 + lane];
            float2 v7 = t2[(size_t)s7 * 32 + lane];
            a.x += v0.x + v1.x + v2.x + v3.x + v4.x + v5.x + v6.x + v7.x;
            a.y += v0.y + v1.y + v2.y + v3.y + v4.y + v5.y + v6.y + v7.y;
        }
        for (; e + 4 <= d; e += 4) {
            int s0 = g_csr[beg + e + 0];
            int s1 = g_csr[beg + e + 1];
            int s2 = g_csr[beg + e + 2];
            int s3 = g_csr[beg + e + 3];
            float2 v0 = t2[(size_t)s0 * 32 + lane];
            float2 v1 = t2[(size_t)s1 * 32 + lane];
            float2 v2 = t2[(size_t)s2 * 32 + lane];
            float2 v3 = t2[(size_t)s3 * 32 + lane];
            a.x += v0.x + v1.x + v2.x + v3.x;
            a.y += v0.y + v1.y + v2.y + v3.y;
        }
        for (; e < d; e++) {
            int s0 = g_csr[beg + e];
            float2 v0 = t2[(size_t)s0 * 32 + lane];
            a.x += v0.x;
            a.y += v0.y;
        }
        float invd = 1.0f / fmaxf((float)d, 1.0f);
        float2* o = &((float2*)g_h2)[(size_t)node * 32 + lane];
        float2 cur = *o;
        cur.x += a.x * invd;
        cur.y += a.y * invd;
        *o = cur;
    }
}

// ------------------------------------------------- layer 1 (combined GEMM, k=128)
// h[:, jb:jb+64] = relu([agg1|x] @ [W1l|W1r](jb:jb+64)^T + b1), gridDim.y picks j-half.
// 4 nodes per warp; float2 weight LDS; broadcast stage LDS. (R8 known-good form.)
__global__ void layer1_kernel(const float* __restrict__ x,
                              const float* __restrict__ W1l,
                              const float* __restrict__ W1r,
                              const float* __restrict__ b1) {
    __shared__ float Wc[128 * 64];      // [k][jl], 32KB
    __shared__ float stage[8][4 * 128]; // per warp: 4 nodes x (agg[64]|x[64]), 16KB

    int tid = threadIdx.x;
    int jb = blockIdx.y * 64;
    for (int idx = tid; idx < 128 * 64; idx += blockDim.x) {
        int jl = idx & 63, k = idx >> 6;
        Wc[k * 64 + jl] = (k < 64) ? W1l[(size_t)(jb + jl) * 64 + k]
                                   : W1r[(size_t)(jb + jl) * 64 + (k - 64)];
    }
    __syncthreads();

    int warp = tid >> 5, lane = tid & 31;
    float* st = stage[warp];
    float2 bv = *(const float2*)&b1[jb + lane * 2];

    int wg = blockIdx.x * 8 + warp;
    int wstride = gridDim.x * 8;
    const int NQUAD = N_NODES / 4;

    for (int q = wg; q < NQUAD; q += wstride) {
        int n0 = q * 4;
#pragma unroll
        for (int n = 0; n < 4; n++) {
            size_t node = (size_t)(n0 + n);
            st[n * 128 + lane]      = g_agg1[node * 64 + lane];
            st[n * 128 + 32 + lane] = g_agg1[node * 64 + 32 + lane];
            st[n * 128 + 64 + lane] = x[node * 64 + lane];
            st[n * 128 + 96 + lane] = x[node * 64 + 32 + lane];
        }
        __syncwarp();

        float a0x = bv.x, a0y = bv.y, a1x = bv.x, a1y = bv.y;
        float a2x = bv.x, a2y = bv.y, a3x = bv.x, a3y = bv.y;
#pragma unroll 4
        for (int k = 0; k < 128; k++) {
            float2 w = *(const float2*)&Wc[k * 64 + lane * 2];
            float s0 = st[k];
            float s1 = st[128 + k];
            float s2 = st[256 + k];
            float s3 = st[384 + k];
            a0x += s0 * w.x; a0y += s0 * w.y;
            a1x += s1 * w.x; a1y += s1 * w.y;
            a2x += s2 * w.x; a2y += s2 * w.y;
            a3x += s3 * w.x; a3y += s3 * w.y;
        }
        float2* hp = (float2*)&g_h[(size_t)n0 * 128 + jb + lane * 2];
        hp[0]   = make_float2(fmaxf(a0x, 0.f), fmaxf(a0y, 0.f));
        hp[64]  = make_float2(fmaxf(a1x, 0.f), fmaxf(a1y, 0.f));
        hp[128] = make_float2(fmaxf(a2x, 0.f), fmaxf(a2y, 0.f));
        hp[192] = make_float2(fmaxf(a3x, 0.f), fmaxf(a3y, 0.f));
        __syncwarp();
    }
}

// ------------------------------------------------- layer 2 (two GEMMs via gridDim.y)
// y=0: g_t = h @ W2l^T (no bias); y=1: g_h2 = h @ W2r^T + b2.
__global__ void layer2_kernel(const float* __restrict__ W2l,
                              const float* __restrict__ W2r,
                              const float* __restrict__ b2) {
    __shared__ float Wc[128 * 64];      // [k][jl], 32KB
    __shared__ float stage[8][4 * 128]; // 4 nodes x h[128], 16KB

    int tid = threadIdx.x;
    int ysel = blockIdx.y;
    const float* W = ysel ? W2r : W2l;
    float* outbuf = ysel ? g_h2 : g_t;
    for (int idx = tid; idx < 128 * 64; idx += blockDim.x) {
        int jl = idx & 63, k = idx >> 6;
        Wc[k * 64 + jl] = W[(size_t)jl * 128 + k];
    }
    __syncthreads();

    int warp = tid >> 5, lane = tid & 31;
    float* st = stage[warp];
    float2 bv = ysel ? *(const float2*)&b2[lane * 2] : make_float2(0.f, 0.f);

    int wg = blockIdx.x * 8 + warp;
    int wstride = gridDim.x * 8;
    const int NQUAD = N_NODES / 4;

    for (int q = wg; q < NQUAD; q += wstride) {
        int n0 = q * 4;
#pragma unroll
        for (int n = 0; n < 4; n++) {
            size_t node = (size_t)(n0 + n);
            st[n * 128 + lane]      = g_h[node * 128 + lane];
            st[n * 128 + 32 + lane] = g_h[node * 128 + 32 + lane];
            st[n * 128 + 64 + lane] = g_h[node * 128 + 64 + lane];
            st[n * 128 + 96 + lane] = g_h[node * 128 + 96 + lane];
        }
        __syncwarp();

        float a0x = bv.x, a0y = bv.y, a1x = bv.x, a1y = bv.y;
        float a2x = bv.x, a2y = bv.y, a3x = bv.x, a3y = bv.y;
#pragma unroll 4
        for (int k = 0; k < 128; k++) {
            float2 w = *(const float2*)&Wc[k * 64 + lane * 2];
            float s0 = st[k];
            float s1 = st[128 + k];
            float s2 = st[256 + k];
            float s3 = st[384 + k];
            a0x += s0 * w.x; a0y += s0 * w.y;
            a1x += s1 * w.x; a1y += s1 * w.y;
            a2x += s2 * w.x; a2y += s2 * w.y;
            a3x += s3 * w.x; a3y += s3 * w.y;
        }
        float2* op = (float2*)&outbuf[(size_t)n0 * 64 + lane * 2];
        op[0]  = make_float2(a0x, a0y);
        op[32] = make_float2(a1x, a1y);
        op[64] = make_float2(a2x, a2y);
        op[96] = make_float2(a3x, a3y);
        __syncwarp();
    }
}

// ------------------------------------------------- link prediction: warp per pair, float2 loads
__global__ void predict_kernel(const int* __restrict__ pairs,
                               const float* __restrict__ Wlp,
                               const float* __restrict__ blp,
                               float* __restrict__ out, int P) {
    int g = blockIdx.x * blockDim.x + threadIdx.x;
    int p = g >> 5;
    int lane = g & 31;
    if (p >= P) return;
    int2 sd = *(const int2*)&pairs[p * 2];
    float2 ws = *(const float2*)&Wlp[lane * 2];
    float2 wd = *(const float2*)&Wlp[64 + lane * 2];
    float2 hs = *(const float2*)&g_h2[(size_t)sd.x * 64 + lane * 2];
    float2 hd = *(const float2*)&g_h2[(size_t)sd.y * 64 + lane * 2];
    float v = hs.x * ws.x + hs.y * ws.y + hd.x * wd.x + hd.y * wd.y;
#pragma unroll
    for (int o = 16; o; o >>= 1) v += __shfl_xor_sync(0xFFFFFFFFu, v, o);
    if (lane == 0) out[p] = 1.0f / (1.0f + expf(-(v + blp[0])));
}

// ----------------------------------------------------------------------------
extern "C" void kernel_launch(void* const* d_in, const int* in_sizes, int n_in,
                              void* d_out, int out_size) {
    const float* x   = (const float*)d_in[0];
    const int* ei    = (const int*)d_in[1];    // int32 (JAX x64 disabled)
    const int* prs   = (const int*)d_in[2];    // int32
    const float* W1l = (const float*)d_in[3];
    const float* W1r = (const float*)d_in[4];
    const float* b1  = (const float*)d_in[5];
    const float* W2l = (const float*)d_in[6];
    const float* W2r = (const float*)d_in[7];
    const float* b2  = (const float*)d_in[8];
    const float* Wlp = (const float*)d_in[9];
    const float* blp = (const float*)d_in[10];
    float* out       = (float*)d_out;

    int E = in_sizes[1] / 2;
    int P = in_sizes[2] / 2;
    int e4blocks = ((E + 3) / 4 + 255) / 256;

    // CSR build
    zero_cnt_kernel<<<(N_NODES + 255) / 256, 256>>>();
    hist_kernel<<<e4blocks, 256>>>(ei, E);
    scan_kernel<<<1, 1024>>>();
    fill_kernel<<<e4blocks, 256>>>(ei, E);

    // Layer 1
    agg1_kernel<<<1024, 256>>>(x);
    dim3 lgrid(256, 2);
    layer1_kernel<<<lgrid, 256>>>(x, W1l, W1r, b1);

    // Layer 2 (linearity: aggregate t = h@W2l^T instead of h)
    layer2_kernel<<<lgrid, 256>>>(W2l, W2r, b2);
    agg2_kernel<<<1024, 256>>>();

    // Link prediction
    int pblocks = (P * 32 + 255) / 256;
    predict_kernel<<<pblocks, 256>>>(prs, Wlp, blp, out, P);
}

// round 14
// speedup vs baseline: 1.4724x; 1.4503x over previous
#include <cuda_runtime.h>
#include <math.h>

#define N_NODES 100000
#define E_MAX   1600000
#define DIN 64
#define DH 128
#define DOUT 64

// Scratch (device globals: allocation-free rule).
__device__ __align__(16) int   g_cnt[N_NODES];
__device__ __align__(16) int   g_start[N_NODES];
__device__ __align__(16) int   g_cur[N_NODES];
__device__ __align__(16) int   g_csr[E_MAX];
__device__ __align__(16) float g_agg1[(size_t)N_NODES * DIN];
__device__ __align__(16) float g_h[(size_t)N_NODES * DH];
__device__ __align__(16) float g_t[(size_t)N_NODES * DOUT];
__device__ __align__(16) float g_h2[(size_t)N_NODES * DOUT];

// ---------------------------------------------------------------- tf32 helpers
__device__ __forceinline__ unsigned f2tf(float f) {
    unsigned u;
    asm("cvt.rna.tf32.f32 %0, %1;" : "=r"(u) : "f"(f));
    return u;
}
// D += A*B, m16n8k8 tf32, A row-major, B col-major (B[n][k] memory layout).
__device__ __forceinline__ void mma_tf32(float* c, const unsigned* a, const unsigned* b) {
    asm("mma.sync.aligned.m16n8k8.row.col.f32.tf32.tf32.f32 "
        "{%0,%1,%2,%3}, {%4,%5,%6,%7}, {%8,%9}, {%0,%1,%2,%3};"
        : "+f"(c[0]), "+f"(c[1]), "+f"(c[2]), "+f"(c[3])
        : "r"(a[0]), "r"(a[1]), "r"(a[2]), "r"(a[3]), "r"(b[0]), "r"(b[1]));
}

// ---------------------------------------------------------------- CSR build (R8)
__global__ void zero_cnt_kernel() {
    int i = blockIdx.x * blockDim.x + threadIdx.x;
    if (i < N_NODES) g_cnt[i] = 0;
}

__global__ void hist_kernel(const int* __restrict__ ei, int E) {
    int i = blockIdx.x * blockDim.x + threadIdx.x;
    int e4 = i * 4;
    if (e4 + 3 < E) {
        int4 d4 = *(const int4*)&ei[E + e4];
        atomicAdd(&g_cnt[d4.x], 1);
        atomicAdd(&g_cnt[d4.y], 1);
        atomicAdd(&g_cnt[d4.z], 1);
        atomicAdd(&g_cnt[d4.w], 1);
    } else {
        for (int e = e4; e < E; e++) atomicAdd(&g_cnt[ei[E + e]], 1);
    }
}

__global__ void scan_kernel() {
    __shared__ int partial[1024];
    int t = threadIdx.x;
    int s = 0;
    if (t < 1000) {
        const int4* c4 = (const int4*)&g_cnt[t * 100];
#pragma unroll
        for (int i = 0; i < 25; i++) {
            int4 v = c4[i];
            s += v.x + v.y + v.z + v.w;
        }
    }
    partial[t] = s;
    __syncthreads();
    for (int off = 1; off < 1024; off <<= 1) {
        int v = partial[t];
        int add = (t >= off) ? partial[t - off] : 0;
        __syncthreads();
        partial[t] = v + add;
        __syncthreads();
    }
    if (t < 1000) {
        int run = (t == 0) ? 0 : partial[t - 1];
        const int4* c4 = (const int4*)&g_cnt[t * 100];
        int4* s4 = (int4*)&g_start[t * 100];
        int4* u4 = (int4*)&g_cur[t * 100];
#pragma unroll
        for (int i = 0; i < 25; i++) {
            int4 c = c4[i];
            int4 st;
            st.x = run; run += c.x;
            st.y = run; run += c.y;
            st.z = run; run += c.z;
            st.w = run; run += c.w;
            s4[i] = st;
            u4[i] = st;
        }
    }
}

__global__ void fill_kernel(const int* __restrict__ ei, int E) {
    int i = blockIdx.x * blockDim.x + threadIdx.x;
    int e4 = i * 4;
    if (e4 + 3 < E) {
        int4 s4 = *(const int4*)&ei[e4];
        int4 d4 = *(const int4*)&ei[E + e4];
        g_csr[atomicAdd(&g_cur[d4.x], 1)] = s4.x;
        g_csr[atomicAdd(&g_cur[d4.y], 1)] = s4.y;
        g_csr[atomicAdd(&g_cur[d4.z], 1)] = s4.z;
        g_csr[atomicAdd(&g_cur[d4.w], 1)] = s4.w;
    } else {
        for (int e = e4; e < E; e++)
            g_csr[atomicAdd(&g_cur[ei[E + e]], 1)] = ei[e];
    }
}

// ------------------------------------------------- aggregation 1 (R8: float2, 4-unroll)
__global__ void agg1_kernel(const float* __restrict__ x) {
    int gw = (blockIdx.x * blockDim.x + threadIdx.x) >> 5;
    int lane = threadIdx.x & 31;
    int nwarps = (gridDim.x * blockDim.x) >> 5;
    const float2* x2 = (const float2*)x;
    for (int node = gw; node < N_NODES; node += nwarps) {
        int beg = g_start[node];
        int d = g_cnt[node];
        float2 a = make_float2(0.f, 0.f);
        int e = 0;
        for (; e + 4 <= d; e += 4) {
            int s0 = g_csr[beg + e + 0];
            int s1 = g_csr[beg + e + 1];
            int s2 = g_csr[beg + e + 2];
            int s3 = g_csr[beg + e + 3];
            float2 v0 = x2[(size_t)s0 * 32 + lane];
            float2 v1 = x2[(size_t)s1 * 32 + lane];
            float2 v2 = x2[(size_t)s2 * 32 + lane];
            float2 v3 = x2[(size_t)s3 * 32 + lane];
            a.x += v0.x + v1.x + v2.x + v3.x;
            a.y += v0.y + v1.y + v2.y + v3.y;
        }
        for (; e < d; e++) {
            int s0 = g_csr[beg + e];
            float2 v0 = x2[(size_t)s0 * 32 + lane];
            a.x += v0.x;
            a.y += v0.y;
        }
        float invd = 1.0f / fmaxf((float)d, 1.0f);
        ((float2*)g_agg1)[(size_t)node * 32 + lane] = make_float2(a.x * invd, a.y * invd);
    }
}

// ------------------------------------------------- aggregation 2 (R8 form)
__global__ void agg2_kernel() {
    int gw = (blockIdx.x * blockDim.x + threadIdx.x) >> 5;
    int lane = threadIdx.x & 31;
    int nwarps = (gridDim.x * blockDim.x) >> 5;
    const float2* t2 = (const float2*)g_t;
    for (int node = gw; node < N_NODES; node += nwarps) {
        int beg = g_start[node];
        int d = g_cnt[node];
        float2 a = make_float2(0.f, 0.f);
        int e = 0;
        for (; e + 4 <= d; e += 4) {
            int s0 = g_csr[beg + e + 0];
            int s1 = g_csr[beg + e + 1];
            int s2 = g_csr[beg + e + 2];
            int s3 = g_csr[beg + e + 3];
            float2 v0 = t2[(size_t)s0 * 32 + lane];
            float2 v1 = t2[(size_t)s1 * 32 + lane];
            float2 v2 = t2[(size_t)s2 * 32 + lane];
            float2 v3 = t2[(size_t)s3 * 32 + lane];
            a.x += v0.x + v1.x + v2.x + v3.x;
            a.y += v0.y + v1.y + v2.y + v3.y;
        }
        for (; e < d; e++) {
            int s0 = g_csr[beg + e];
            float2 v0 = t2[(size_t)s0 * 32 + lane];
            a.x += v0.x;
            a.y += v0.y;
        }
        float invd = 1.0f / fmaxf((float)d, 1.0f);
        float2* o = &((float2*)g_h2)[(size_t)node * 32 + lane];
        float2 cur = *o;
        cur.x += a.x * invd;
        cur.y += a.y * invd;
        *o = cur;
    }
}

// ------------------------------------------------- layer 1 via tf32 MMA
// h = relu([agg1|x] @ [W1l|W1r]^T + b1).  A: [100k x 128] (k<64: agg1, k>=64: x).
// Ws[j][k] (col-major B), stride 132 words (4j+k bank map, conflict-free).
// Block: 256 thr, 8 warps; warp tile m32 x j32; m-tile 64 nodes per iteration.
#define LW_STRIDE 132
#define NM_TILES 1563   // ceil(100000/64)

__global__ void __launch_bounds__(256, 2)
layer1_mma_kernel(const float* __restrict__ x,
                  const float* __restrict__ W1l,
                  const float* __restrict__ W1r,
                  const float* __restrict__ b1) {
    extern __shared__ unsigned sm[];
    unsigned* Ws = sm;                    // [128][132]
    unsigned* As = sm + 128 * LW_STRIDE;  // [64][132]

    int tid = threadIdx.x;
    for (int idx = tid; idx < 128 * 128; idx += 256) {
        int j = idx >> 7, k = idx & 127;
        float w = (k < 64) ? W1l[(size_t)j * 64 + k] : W1r[(size_t)j * 64 + (k - 64)];
        Ws[j * LW_STRIDE + k] = f2tf(w);
    }

    int warp = tid >> 5, lane = tid & 31;
    int grp = lane >> 2, tig = lane & 3;
    int m_off = (warp & 1) * 32;
    int j_off = (warp >> 1) * 32;

    // bias per thread (cols j_off+ni*8+2tig, +1)
    float2 bv[4];
#pragma unroll
    for (int ni = 0; ni < 4; ni++) {
        int c = j_off + ni * 8 + 2 * tig;
        bv[ni] = make_float2(b1[c], b1[c + 1]);
    }
    __syncthreads();

    for (int mt = blockIdx.x; mt < NM_TILES; mt += gridDim.x) {
        int mbase = mt * 64;
        // stage A tile (64 x 128) with tf32 rounding
        for (int idx = tid; idx < 64 * 128; idx += 256) {
            int r = idx >> 7, k = idx & 127;
            int node = mbase + r;
            float v = 0.f;
            if (node < N_NODES)
                v = (k < 64) ? g_agg1[(size_t)node * 64 + k]
                             : x[(size_t)node * 64 + (k - 64)];
            As[r * LW_STRIDE + k] = f2tf(v);
        }
        __syncthreads();

        float acc[2][4][4];
#pragma unroll
        for (int mi = 0; mi < 2; mi++)
#pragma unroll
            for (int ni = 0; ni < 4; ni++)
#pragma unroll
                for (int q = 0; q < 4; q++) acc[mi][ni][q] = 0.f;

#pragma unroll 4
        for (int ks = 0; ks < 16; ks++) {
            int kb = ks * 8;
            unsigned a[2][4];
#pragma unroll
            for (int mi = 0; mi < 2; mi++) {
                int m = m_off + mi * 16;
                a[mi][0] = As[(m + grp) * LW_STRIDE + kb + tig];
                a[mi][1] = As[(m + 8 + grp) * LW_STRIDE + kb + tig];
                a[mi][2] = As[(m + grp) * LW_STRIDE + kb + tig + 4];
                a[mi][3] = As[(m + 8 + grp) * LW_STRIDE + kb + tig + 4];
            }
            unsigned b[4][2];
#pragma unroll
            for (int ni = 0; ni < 4; ni++) {
                int j = j_off + ni * 8;
                b[ni][0] = Ws[(j + grp) * LW_STRIDE + kb + tig];
                b[ni][1] = Ws[(j + grp) * LW_STRIDE + kb + tig + 4];
            }
#pragma unroll
            for (int mi = 0; mi < 2; mi++)
#pragma unroll
                for (int ni = 0; ni < 4; ni++)
                    mma_tf32(acc[mi][ni], a[mi], b[ni]);
        }
        __syncthreads();  // before next stage overwrites As

        // epilogue: relu(acc + bias) -> g_h
#pragma unroll
        for (int mi = 0; mi < 2; mi++) {
            int r0 = mbase + m_off + mi * 16 + grp;
            int r1 = r0 + 8;
#pragma unroll
            for (int ni = 0; ni < 4; ni++) {
                int c = j_off + ni * 8 + 2 * tig;
                if (r0 < N_NODES) {
                    float2 o0 = make_float2(fmaxf(acc[mi][ni][0] + bv[ni].x, 0.f),
                                            fmaxf(acc[mi][ni][1] + bv[ni].y, 0.f));
                    *(float2*)&g_h[(size_t)r0 * 128 + c] = o0;
                }
                if (r1 < N_NODES) {
                    float2 o1 = make_float2(fmaxf(acc[mi][ni][2] + bv[ni].x, 0.f),
                                            fmaxf(acc[mi][ni][3] + bv[ni].y, 0.f));
                    *(float2*)&g_h[(size_t)r1 * 128 + c] = o1;
                }
            }
        }
    }
}

// ------------------------------------------------- layer 2 via tf32 MMA
// Ws rows j<64: W2l (-> g_t, no bias); j>=64: W2r (-> g_h2, +b2).
__global__ void __launch_bounds__(256, 2)
layer2_mma_kernel(const float* __restrict__ W2l,
                  const float* __restrict__ W2r,
                  const float* __restrict__ b2) {
    extern __shared__ unsigned sm[];
    unsigned* Ws = sm;                    // [128][132]
    unsigned* As = sm + 128 * LW_STRIDE;  // [64][132]

    int tid = threadIdx.x;
    for (int idx = tid; idx < 128 * 128; idx += 256) {
        int j = idx >> 7, k = idx & 127;
        float w = (j < 64) ? W2l[(size_t)j * 128 + k] : W2r[(size_t)(j - 64) * 128 + k];
        Ws[j * LW_STRIDE + k] = f2tf(w);
    }

    int warp = tid >> 5, lane = tid & 31;
    int grp = lane >> 2, tig = lane & 3;
    int m_off = (warp & 1) * 32;
    int j_off = (warp >> 1) * 32;
    int to_h2 = (j_off >= 64);            // warps 4-7 write g_h2 (+bias)
    int jl_off = j_off & 63;

    float2 bv[4];
#pragma unroll
    for (int ni = 0; ni < 4; ni++) {
        int cl = jl_off + ni * 8 + 2 * tig;
        bv[ni] = to_h2 ? make_float2(b2[cl], b2[cl + 1]) : make_float2(0.f, 0.f);
    }
    __syncthreads();

    float* obase = to_h2 ? g_h2 : g_t;

    for (int mt = blockIdx.x; mt < NM_TILES; mt += gridDim.x) {
        int mbase = mt * 64;
        for (int idx = tid; idx < 64 * 128; idx += 256) {
            int r = idx >> 7, k = idx & 127;
            int node = mbase + r;
            float v = (node < N_NODES) ? g_h[(size_t)node * 128 + k] : 0.f;
            As[r * LW_STRIDE + k] = f2tf(v);
        }
        __syncthreads();

        float acc[2][4][4];
#pragma unroll
        for (int mi = 0; mi < 2; mi++)
#pragma unroll
            for (int ni = 0; ni < 4; ni++)
#pragma unroll
                for (int q = 0; q < 4; q++) acc[mi][ni][q] = 0.f;

#pragma unroll 4
        for (int ks = 0; ks < 16; ks++) {
            int kb = ks * 8;
            unsigned a[2][4];
#pragma unroll
            for (int mi = 0; mi < 2; mi++) {
                int m = m_off + mi * 16;
                a[mi][0] = As[(m + grp) * LW_STRIDE + kb + tig];
                a[mi][1] = As[(m + 8 + grp) * LW_STRIDE + kb + tig];
                a[mi][2] = As[(m + grp) * LW_STRIDE + kb + tig + 4];
                a[mi][3] = As[(m + 8 + grp) * LW_STRIDE + kb + tig + 4];
            }
            unsigned b[4][2];
#pragma unroll
            for (int ni = 0; ni < 4; ni++) {
                int j = j_off + ni * 8;
                b[ni][0] = Ws[(j + grp) * LW_STRIDE + kb + tig];
                b[ni][1] = Ws[(j + grp) * LW_STRIDE + kb + tig + 4];
            }
#pragma unroll
            for (int mi = 0; mi < 2; mi++)
#pragma unroll
                for (int ni = 0; ni < 4; ni++)
                    mma_tf32(acc[mi][ni], a[mi], b[ni]);
        }
        __syncthreads();

#pragma unroll
        for (int mi = 0; mi < 2; mi++) {
            int r0 = mbase + m_off + mi * 16 + grp;
            int r1 = r0 + 8;
#pragma unroll
            for (int ni = 0; ni < 4; ni++) {
                int cl = jl_off + ni * 8 + 2 * tig;
                if (r0 < N_NODES) {
                    float2 o0 = make_float2(acc[mi][ni][0] + bv[ni].x,
                                            acc[mi][ni][1] + bv[ni].y);
                    *(float2*)&obase[(size_t)r0 * 64 + cl] = o0;
                }
                if (r1 < N_NODES) {
                    float2 o1 = make_float2(acc[mi][ni][2] + bv[ni].x,
                                            acc[mi][ni][3] + bv[ni].y);
                    *(float2*)&obase[(size_t)r1 * 64 + cl] = o1;
                }
            }
        }
    }
}

// ------------------------------------------------- link prediction (R8 form)
__global__ void predict_kernel(const int* __restrict__ pairs,
                               const float* __restrict__ Wlp,
                               const float* __restrict__ blp,
                               float* __restrict__ out, int P) {
    int g = blockIdx.x * blockDim.x + threadIdx.x;
    int p = g >> 5;
    int lane = g & 31;
    if (p >= P) return;
    int2 sd = *(const int2*)&pairs[p * 2];
    float w0 = Wlp[lane], w1 = Wlp[lane + 32], w2 = Wlp[lane + 64], w3 = Wlp[lane + 96];
    float v = g_h2[(size_t)sd.x * 64 + lane] * w0
            + g_h2[(size_t)sd.x * 64 + lane + 32] * w1
            + g_h2[(size_t)sd.y * 64 + lane] * w2
            + g_h2[(size_t)sd.y * 64 + lane + 32] * w3;
#pragma unroll
    for (int o = 16; o; o >>= 1) v += __shfl_xor_sync(0xFFFFFFFFu, v, o);
    if (lane == 0) out[p] = 1.0f / (1.0f + expf(-(v + blp[0])));
}

// ----------------------------------------------------------------------------
extern "C" void kernel_launch(void* const* d_in, const int* in_sizes, int n_in,
                              void* d_out, int out_size) {
    const float* x   = (const float*)d_in[0];
    const int* ei    = (const int*)d_in[1];    // int32 (JAX x64 disabled)
    const int* prs   = (const int*)d_in[2];    // int32
    const float* W1l = (const float*)d_in[3];
    const float* W1r = (const float*)d_in[4];
    const float* b1  = (const float*)d_in[5];
    const float* W2l = (const float*)d_in[6];
    const float* W2r = (const float*)d_in[7];
    const float* b2  = (const float*)d_in[8];
    const float* Wlp = (const float*)d_in[9];
    const float* blp = (const float*)d_in[10];
    float* out       = (float*)d_out;

    int E = in_sizes[1] / 2;
    int P = in_sizes[2] / 2;
    int e4blocks = ((E + 3) / 4 + 255) / 256;

    size_t lsmem = (size_t)(128 + 64) * LW_STRIDE * sizeof(unsigned);  // 101376B
    cudaFuncSetAttribute(layer1_mma_kernel, cudaFuncAttributeMaxDynamicSharedMemorySize, (int)lsmem);
    cudaFuncSetAttribute(layer2_mma_kernel, cudaFuncAttributeMaxDynamicSharedMemorySize, (int)lsmem);

    // CSR build
    zero_cnt_kernel<<<(N_NODES + 255) / 256, 256>>>();
    hist_kernel<<<e4blocks, 256>>>(ei, E);
    scan_kernel<<<1, 1024>>>();
    fill_kernel<<<e4blocks, 256>>>(ei, E);

    // Layer 1
    agg1_kernel<<<1024, 256>>>(x);
    layer1_mma_kernel<<<296, 256, lsmem>>>(x, W1l, W1r, b1);

    // Layer 2 (linearity: aggregate t = h@W2l^T instead of h)
    layer2_mma_kernel<<<296, 256, lsmem>>>(W2l, W2r, b2);
    agg2_kernel<<<1024, 256>>>();

    // Link prediction
    int pblocks = (P * 32 + 255) / 256;
    predict_kernel<<<pblocks, 256>>>(prs, Wlp, blp, out, P);
}